// round 15
// baseline (speedup 1.0000x reference)
#include <cuda_runtime.h>

// ---------------- problem-size constants (max) ----------------
#define N_MAX 100000
#define E_MAX 1600000

// ---------------- scratch (device globals; no allocation allowed) ----------
__device__ float g_deg [N_MAX];            // dinv
__device__ float g_y   [N_MAX * 64];       // dinv * (rep @ W1)
__device__ float g_y2  [N_MAX * 64];       // dinv * (h1 @ W2)
__device__ float g_h   [N_MAX * 64];       // h1 then h2
__device__ float g_t1  [N_MAX * 128];      // MLP hidden 1 (pre, then final)
__device__ int   g_cnt [N_MAX];            // dst histogram
__device__ int   g_rp  [N_MAX + 1];        // CSR row pointers (by dst)
__device__ int   g_wp  [N_MAX];            // fill write pointers
__device__ int   g_eidx[E_MAX];            // src ids grouped by dst
__device__ int   g_bsum[256];              // scan block partials

// ---------------- CSR build ----------------
__global__ void k_hist(const int* __restrict__ dst, int* __restrict__ cnt, int E) {
    int i = blockIdx.x * blockDim.x + threadIdx.x;
    if (i < E) atomicAdd(&cnt[dst[i]], 1);
}

__global__ void k_scan1(const int* __restrict__ cnt, int* __restrict__ rp,
                        int* __restrict__ bsum, int N) {
    __shared__ int wsum[8];
    __shared__ int btot;
    int t = threadIdx.x, lane = t & 31, w = t >> 5;
    int base = blockIdx.x * 1024 + t * 4;
    int v0 = (base + 0 < N) ? cnt[base + 0] : 0;
    int v1 = (base + 1 < N) ? cnt[base + 1] : 0;
    int v2 = (base + 2 < N) ? cnt[base + 2] : 0;
    int v3 = (base + 3 < N) ? cnt[base + 3] : 0;
    int s = v0 + v1 + v2 + v3;
    int x = s;
    #pragma unroll
    for (int o = 1; o < 32; o <<= 1) {
        int y = __shfl_up_sync(0xffffffffu, x, o);
        if (lane >= o) x += y;
    }
    if (lane == 31) wsum[w] = x;
    __syncthreads();
    if (t == 0) {
        int a = 0;
        #pragma unroll
        for (int i = 0; i < 8; ++i) { int tmp = wsum[i]; wsum[i] = a; a += tmp; }
        btot = a;
    }
    __syncthreads();
    int off = (x - s) + wsum[w];
    if (base + 0 < N) rp[base + 0] = off;
    if (base + 1 < N) rp[base + 1] = off + v0;
    if (base + 2 < N) rp[base + 2] = off + v0 + v1;
    if (base + 3 < N) rp[base + 3] = off + v0 + v1 + v2;
    if (t == 0) bsum[blockIdx.x] = btot;
}

// fused scan2+scan3
__global__ void k_scan23(const int* __restrict__ cnt, int* __restrict__ rp,
                         int* __restrict__ wp, float* __restrict__ dinv,
                         const int* __restrict__ bsum, int nB, int N, int E) {
    __shared__ int sb[128];
    __shared__ int ws[4];
    int t = threadIdx.x, lane = t & 31, w = t >> 5;
    int v = (t < nB) ? bsum[t] : 0;
    int x = v;
    #pragma unroll
    for (int o = 1; o < 32; o <<= 1) {
        int y = __shfl_up_sync(0xffffffffu, x, o);
        if (lane >= o) x += y;
    }
    if (lane == 31 && w < 4) ws[w] = x;
    __syncthreads();
    if (t == 0) {
        int a = 0;
        #pragma unroll
        for (int i = 0; i < 4; ++i) { int tmp = ws[i]; ws[i] = a; a += tmp; }
    }
    __syncthreads();
    if (t < 128) sb[t] = (x - v) + ws[w];
    __syncthreads();

    int i = blockIdx.x * blockDim.x + t;
    if (i < N) {
        int r = rp[i] + sb[i >> 10];
        rp[i] = r;
        wp[i] = r;
        dinv[i] = rsqrtf((float)cnt[i] + 2.0f);
    }
    if (i == 0) rp[N] = E;
}

__global__ void k_fill(const int* __restrict__ src, const int* __restrict__ dst,
                       int* __restrict__ wp, int* __restrict__ eidx, int E) {
    int i = blockIdx.x * blockDim.x + threadIdx.x;
    if (i < E) {
        int pos = atomicAdd(&wp[dst[i]], 1);
        eidx[pos] = src[i];
    }
}

// ---------------- fused gather + epilogue ----------------
// PDL consumer: waits on predecessor grid before touching y.
__global__ void k_gather(const float* __restrict__ y, const int* __restrict__ rp,
                         const int* __restrict__ eidx, const float* __restrict__ dinv,
                         const float* __restrict__ b, float* __restrict__ h, int N) {
    cudaGridDependencySynchronize();

    int warp = (blockIdx.x * blockDim.x + threadIdx.x) >> 5;
    int lane = threadIdx.x & 31;
    if (warp >= N) return;
    const int c = lane * 2;
    int beg = rp[warp], end = rp[warp + 1];

    float2 a0 = *(const float2*)(y + (size_t)warp * 64 + c);
    a0.x *= 2.0f; a0.y *= 2.0f;
    float2 a1 = make_float2(0.f, 0.f);
    float2 a2 = make_float2(0.f, 0.f);
    float2 a3 = make_float2(0.f, 0.f);

    for (int j0 = beg; j0 < end; j0 += 32) {
        int myj = j0 + lane;
        int sreg = (myj < end) ? eidx[myj] : 0;
        int n = min(32, end - j0);
        int t = 0;
        for (; t + 3 < n; t += 4) {
            int s0 = __shfl_sync(0xffffffffu, sreg, t);
            int s1 = __shfl_sync(0xffffffffu, sreg, t + 1);
            int s2 = __shfl_sync(0xffffffffu, sreg, t + 2);
            int s3 = __shfl_sync(0xffffffffu, sreg, t + 3);
            float2 v0 = *(const float2*)(y + (size_t)s0 * 64 + c);
            float2 v1 = *(const float2*)(y + (size_t)s1 * 64 + c);
            float2 v2 = *(const float2*)(y + (size_t)s2 * 64 + c);
            float2 v3 = *(const float2*)(y + (size_t)s3 * 64 + c);
            a0.x += v0.x; a0.y += v0.y;
            a1.x += v1.x; a1.y += v1.y;
            a2.x += v2.x; a2.y += v2.y;
            a3.x += v3.x; a3.y += v3.y;
        }
        for (; t < n; ++t) {
            int s0 = __shfl_sync(0xffffffffu, sreg, t);
            float2 v0 = *(const float2*)(y + (size_t)s0 * 64 + c);
            a0.x += v0.x; a0.y += v0.y;
        }
    }
    float d = dinv[warp];
    float sx = (a0.x + a1.x) + (a2.x + a3.x);
    float sy = (a0.y + a1.y) + (a2.y + a3.y);
    float2 o;
    o.x = fmaxf(d * sx + b[c],     0.0f);
    o.y = fmaxf(d * sy + b[c + 1], 0.0f);
    *(float2*)(h + (size_t)warp * 64 + c) = o;
}

// ---------------- 3xTF32 helpers ----------------
__device__ __forceinline__ unsigned f2tf(float a) {
    unsigned r;
    asm("cvt.rna.tf32.f32 %0, %1;" : "=r"(r) : "f"(a));
    return r;
}

__device__ __forceinline__ void mma8(float* c, unsigned a0, unsigned a1,
                                     unsigned a2, unsigned a3,
                                     unsigned b0, unsigned b1) {
    asm("mma.sync.aligned.m16n8k8.row.col.f32.tf32.tf32.f32 "
        "{%0,%1,%2,%3},{%4,%5,%6,%7},{%8,%9},{%0,%1,%2,%3};"
        : "+f"(c[0]), "+f"(c[1]), "+f"(c[2]), "+f"(c[3])
        : "r"(a0), "r"(a1), "r"(a2), "r"(a3), "r"(b0), "r"(b1));
}

// ---------------- 3xTF32 tensor-core GEMM (R8 configuration) --------------
// PDL: stages W first (independent of predecessor), THEN grid-syncs, then
// stages X (predecessor's output).
template<int K, int M, bool PRESCALE, bool BIAS, bool RELU, bool ADDIN>
__global__ void __launch_bounds__(256)
k_gemm(const float* __restrict__ X0, const float* __restrict__ W,
       const float* __restrict__ bias, const float* __restrict__ dinv,
       const float* __restrict__ ADD, float* __restrict__ OUT, int N) {
    constexpr int ROWS = 64;
    constexpr int WSTR = M + 8;
    constexpr int XSTR = K + 4;
    constexpr int CPW  = M / 2;
    constexpr int NT   = CPW / 8;
    constexpr int KC   = K / 8;

    extern __shared__ float sm[];
    float* Wsm = sm;                     // K * WSTR
    float* Xs  = sm + K * WSTR;          // ROWS * XSTR

    for (int i = threadIdx.x; i < K * M; i += 256)
        Wsm[(i / M) * WSTR + (i % M)] = W[i];

    cudaGridDependencySynchronize();     // predecessor's writes now visible

    const int lane = threadIdx.x & 31;
    const int warp = threadIdx.x >> 5;
    const int q = lane & 3;
    const int g = lane >> 2;
    const int wr = warp & 3;
    const int wc = warp >> 2;
    const int cb = wc * CPW;
    const int row0 = blockIdx.x * ROWS;

    __syncthreads();
    for (int i = threadIdx.x; i < ROWS * K; i += 256) {
        int r = i / K, c = i % K;
        int gr = row0 + r;
        Xs[r * XSTR + c] = (gr < N) ? X0[(size_t)gr * K + c] : 0.f;
    }
    __syncthreads();

    float acc[NT][4];
    #pragma unroll
    for (int nt = 0; nt < NT; ++nt)
        #pragma unroll
        for (int j = 0; j < 4; ++j) acc[nt][j] = 0.f;

    const int ar0 = wr * 16 + g;
    #pragma unroll
    for (int kc = 0; kc < KC; ++kc) {
        const int k0 = kc * 8 + q;
        float a0f = Xs[ar0 * XSTR + k0];
        float a1f = Xs[(ar0 + 8) * XSTR + k0];
        float a2f = Xs[ar0 * XSTR + k0 + 4];
        float a3f = Xs[(ar0 + 8) * XSTR + k0 + 4];
        unsigned ah0 = f2tf(a0f), ah1 = f2tf(a1f), ah2 = f2tf(a2f), ah3 = f2tf(a3f);
        unsigned al0 = f2tf(a0f - __uint_as_float(ah0));
        unsigned al1 = f2tf(a1f - __uint_as_float(ah1));
        unsigned al2 = f2tf(a2f - __uint_as_float(ah2));
        unsigned al3 = f2tf(a3f - __uint_as_float(ah3));

        #pragma unroll
        for (int nt = 0; nt < NT; ++nt) {
            int n = cb + nt * 8 + g;
            float b0f = Wsm[k0 * WSTR + n];
            float b1f = Wsm[(k0 + 4) * WSTR + n];
            unsigned bh0 = f2tf(b0f), bh1 = f2tf(b1f);
            unsigned bl0 = f2tf(b0f - __uint_as_float(bh0));
            unsigned bl1 = f2tf(b1f - __uint_as_float(bh1));
            mma8(acc[nt], al0, al1, al2, al3, bh0, bh1);  // Al*Bh
            mma8(acc[nt], ah0, ah1, ah2, ah3, bl0, bl1);  // Ah*Bl
            mma8(acc[nt], ah0, ah1, ah2, ah3, bh0, bh1);  // Ah*Bh
        }
    }

    int r0 = row0 + ar0;
    int r1 = r0 + 8;
    float s0 = 1.f, s1 = 1.f;
    if (PRESCALE) {
        if (r0 < N) s0 = dinv[r0];
        if (r1 < N) s1 = dinv[r1];
    }
    #pragma unroll
    for (int nt = 0; nt < NT; ++nt) {
        int col = cb + nt * 8 + 2 * q;
        float2 o0 = make_float2(acc[nt][0], acc[nt][1]);
        float2 o1 = make_float2(acc[nt][2], acc[nt][3]);
        if (PRESCALE) { o0.x *= s0; o0.y *= s0; o1.x *= s1; o1.y *= s1; }
        if (ADDIN) {
            if (r0 < N) {
                float2 p = *(const float2*)(ADD + (size_t)r0 * M + col);
                o0.x += p.x; o0.y += p.y;
            }
            if (r1 < N) {
                float2 p = *(const float2*)(ADD + (size_t)r1 * M + col);
                o1.x += p.x; o1.y += p.y;
            }
        }
        if (BIAS) {
            float2 b2 = *(const float2*)(bias + col);
            o0.x += b2.x; o0.y += b2.y;
            o1.x += b2.x; o1.y += b2.y;
        }
        if (RELU) {
            o0.x = fmaxf(o0.x, 0.f); o0.y = fmaxf(o0.y, 0.f);
            o1.x = fmaxf(o1.x, 0.f); o1.y = fmaxf(o1.y, 0.f);
        }
        if (r0 < N) *(float2*)(OUT + (size_t)r0 * M + col) = o0;
        if (r1 < N) *(float2*)(OUT + (size_t)r1 * M + col) = o1;
    }
}

// ---------------- JAX partitionable threefry2x32 (key = [0, 42]) ----------
__device__ __forceinline__ unsigned rotl32(unsigned v, int r) {
    return (v << r) | (v >> (32 - r));
}

__device__ __forceinline__ uint2 threefry(unsigned c0, unsigned c1) {
    const unsigned k0 = 0u, k1 = 42u;
    const unsigned k2 = k0 ^ k1 ^ 0x1BD11BDAu;
    unsigned x0 = c0 + k0, x1 = c1 + k1;
#define TF_RND(r) { x0 += x1; x1 = rotl32(x1, r); x1 ^= x0; }
    TF_RND(13) TF_RND(15) TF_RND(26) TF_RND(6)
    x0 += k1; x1 += k2 + 1u;
    TF_RND(17) TF_RND(29) TF_RND(16) TF_RND(24)
    x0 += k2; x1 += k0 + 2u;
    TF_RND(13) TF_RND(15) TF_RND(26) TF_RND(6)
    x0 += k0; x1 += k1 + 3u;
    TF_RND(17) TF_RND(29) TF_RND(16) TF_RND(24)
    x0 += k1; x1 += k2 + 4u;
    TF_RND(13) TF_RND(15) TF_RND(26) TF_RND(6)
    x0 += k2; x1 += k0 + 5u;
#undef TF_RND
    return make_uint2(x0, x1);
}

__device__ __forceinline__ unsigned tf_bits_part(unsigned i) {
    uint2 o = threefry(0u, i);
    return o.x ^ o.y;
}

__device__ __forceinline__ float bits_to_uniform(unsigned b) {
    float f = __uint_as_float((b >> 9) | 0x3f800000u) - 1.0f;
    f = f + 1e-20f;
    return fmaxf(f, 1e-20f);
}

// ---------------- fused MLP2 + final (gemm K=128,M=64 + sigmoid/gumbel) ----
__global__ void __launch_bounds__(256)
k_mlp2final(const float* __restrict__ X0, const float* __restrict__ W,
            const float* __restrict__ bias, const float* __restrict__ Wo,
            const float* __restrict__ bo, float* __restrict__ out, int N) {
    constexpr int K = 128, M = 64, ROWS = 64;
    constexpr int WSTR = M + 8;
    constexpr int XSTR = K + 4;
    constexpr int CPW  = M / 2;
    constexpr int NT   = CPW / 8;
    constexpr int KC   = K / 8;
    constexpr int TSTR = 66;

    extern __shared__ float sm[];
    float* Wsm = sm;
    float* Xs  = sm + K * WSTR;
    float* t2s = Xs;

    __shared__ float ws[64];
    __shared__ float bos;

    for (int i = threadIdx.x; i < K * M; i += 256)
        Wsm[(i / M) * WSTR + (i % M)] = W[i];
    if (threadIdx.x < 64) ws[threadIdx.x] = Wo[threadIdx.x];
    if (threadIdx.x == 0) bos = bo[0];

    cudaGridDependencySynchronize();     // predecessor (mlp1b) now complete

    const int lane = threadIdx.x & 31;
    const int warp = threadIdx.x >> 5;
    const int q = lane & 3;
    const int g = lane >> 2;
    const int wr = warp & 3;
    const int wc = warp >> 2;
    const int cb = wc * CPW;
    const int row0 = blockIdx.x * ROWS;

    __syncthreads();
    for (int i = threadIdx.x; i < ROWS * K; i += 256) {
        int r = i / K, c = i % K;
        int gr = row0 + r;
        Xs[r * XSTR + c] = (gr < N) ? X0[(size_t)gr * K + c] : 0.f;
    }
    __syncthreads();

    float acc[NT][4];
    #pragma unroll
    for (int nt = 0; nt < NT; ++nt)
        #pragma unroll
        for (int j = 0; j < 4; ++j) acc[nt][j] = 0.f;

    const int ar0 = wr * 16 + g;
    #pragma unroll
    for (int kc = 0; kc < KC; ++kc) {
        const int k0 = kc * 8 + q;
        float a0f = Xs[ar0 * XSTR + k0];
        float a1f = Xs[(ar0 + 8) * XSTR + k0];
        float a2f = Xs[ar0 * XSTR + k0 + 4];
        float a3f = Xs[(ar0 + 8) * XSTR + k0 + 4];
        unsigned ah0 = f2tf(a0f), ah1 = f2tf(a1f), ah2 = f2tf(a2f), ah3 = f2tf(a3f);
        unsigned al0 = f2tf(a0f - __uint_as_float(ah0));
        unsigned al1 = f2tf(a1f - __uint_as_float(ah1));
        unsigned al2 = f2tf(a2f - __uint_as_float(ah2));
        unsigned al3 = f2tf(a3f - __uint_as_float(ah3));

        #pragma unroll
        for (int nt = 0; nt < NT; ++nt) {
            int n = cb + nt * 8 + g;
            float b0f = Wsm[k0 * WSTR + n];
            float b1f = Wsm[(k0 + 4) * WSTR + n];
            unsigned bh0 = f2tf(b0f), bh1 = f2tf(b1f);
            unsigned bl0 = f2tf(b0f - __uint_as_float(bh0));
            unsigned bl1 = f2tf(b1f - __uint_as_float(bh1));
            mma8(acc[nt], al0, al1, al2, al3, bh0, bh1);
            mma8(acc[nt], ah0, ah1, ah2, ah3, bl0, bl1);
            mma8(acc[nt], ah0, ah1, ah2, ah3, bh0, bh1);
        }
    }

    __syncthreads();

    #pragma unroll
    for (int nt = 0; nt < NT; ++nt) {
        int col = cb + nt * 8 + 2 * q;
        float2 b2 = *(const float2*)(bias + col);
        float2 o0 = make_float2(fmaxf(acc[nt][0] + b2.x, 0.f),
                                fmaxf(acc[nt][1] + b2.y, 0.f));
        float2 o1 = make_float2(fmaxf(acc[nt][2] + b2.x, 0.f),
                                fmaxf(acc[nt][3] + b2.y, 0.f));
        *(float2*)(t2s + ar0 * TSTR + col)       = o0;
        *(float2*)(t2s + (ar0 + 8) * TSTR + col) = o1;
    }
    __syncthreads();

    for (int rloc = warp; rloc < ROWS; rloc += 8) {
        int gr = row0 + rloc;
        if (gr >= N) continue;
        const float* row = t2s + rloc * TSTR;
        float s = row[lane] * ws[lane] + row[lane + 32] * ws[lane + 32];
        #pragma unroll
        for (int o = 16; o; o >>= 1) s += __shfl_xor_sync(0xffffffffu, s, o);

        float p = 1.0f / (1.0f + expf(-(s + bos)));

        float gn = 0.0f;
        if (lane < 2) {
            unsigned f = 2u * (unsigned)gr + (unsigned)lane;
            float u = bits_to_uniform(tf_bits_part(f));
            gn = -logf(-logf(u));
        }
        float g0 = __shfl_sync(0xffffffffu, gn, 0);
        float g1 = __shfl_sync(0xffffffffu, gn, 1);

        if (lane == 0) {
            out[gr]     = p;
            out[N + gr] = ((p + g1) > ((1.0f - p) + g0)) ? 1.0f : 0.0f;
        }
    }
}

// ---------------- launch ----------------
extern "C" void kernel_launch(void* const* d_in, const int* in_sizes, int n_in,
                              void* d_out, int out_size) {
    const float* rep = (const float*)d_in[0];
    const int*   ei  = (const int*)  d_in[1];
    const float* W1  = (const float*)d_in[2];
    const float* b1  = (const float*)d_in[3];
    const float* W2  = (const float*)d_in[4];
    const float* b2  = (const float*)d_in[5];
    const float* Wa  = (const float*)d_in[6];
    const float* ba  = (const float*)d_in[7];
    const float* Wb  = (const float*)d_in[8];
    const float* bb  = (const float*)d_in[9];
    const float* Wo  = (const float*)d_in[10];
    const float* bo  = (const float*)d_in[11];
    float* out = (float*)d_out;

    int N = in_sizes[0] / 64;
    int E = in_sizes[1] / 2;
    if (N > N_MAX || E > E_MAX) return;
    const int* src = ei;
    const int* dst = ei + E;

    float *dinv, *y, *y2, *h, *t1;
    int *cnt, *rp, *wp, *eidx, *bsum;
    cudaGetSymbolAddress((void**)&dinv, g_deg);
    cudaGetSymbolAddress((void**)&y,    g_y);
    cudaGetSymbolAddress((void**)&y2,   g_y2);
    cudaGetSymbolAddress((void**)&h,    g_h);
    cudaGetSymbolAddress((void**)&t1,   g_t1);
    cudaGetSymbolAddress((void**)&cnt,  g_cnt);
    cudaGetSymbolAddress((void**)&rp,   g_rp);
    cudaGetSymbolAddress((void**)&wp,   g_wp);
    cudaGetSymbolAddress((void**)&eidx, g_eidx);
    cudaGetSymbolAddress((void**)&bsum, g_bsum);

    // streams + events: created once, on the (uncaptured) correctness call
    static cudaStream_t s1 = nullptr, s2 = nullptr;
    static cudaEvent_t evStart = nullptr, evDinv = nullptr, evFill = nullptr, evPre = nullptr;
    if (!s1) {
        cudaStreamCreateWithFlags(&s1, cudaStreamNonBlocking);
        cudaStreamCreateWithFlags(&s2, cudaStreamNonBlocking);
        cudaEventCreateWithFlags(&evStart, cudaEventDisableTiming);
        cudaEventCreateWithFlags(&evDinv,  cudaEventDisableTiming);
        cudaEventCreateWithFlags(&evFill,  cudaEventDisableTiming);
        cudaEventCreateWithFlags(&evPre,   cudaEventDisableTiming);
    }

    // dynamic smem: W K*(M+8) + X 64*(K+4)
    const int SM_G64     = (64 * 72  + 64 * 68)  * 4;   // 35.8 KB
    const int SM_K64M128 = (64 * 136 + 64 * 68)  * 4;   // 52.2 KB
    const int SM_MLP2    = (128 * 72 + 64 * 132) * 4;   // 70.7 KB
    cudaFuncSetAttribute((const void*)k_gemm<64,64,true,false,false,false>,
                         cudaFuncAttributeMaxDynamicSharedMemorySize, SM_G64);
    cudaFuncSetAttribute((const void*)k_gemm<64,128,false,false,false,false>,
                         cudaFuncAttributeMaxDynamicSharedMemorySize, SM_K64M128);
    cudaFuncSetAttribute((const void*)k_gemm<64,128,false,true,true,true>,
                         cudaFuncAttributeMaxDynamicSharedMemorySize, SM_K64M128);
    cudaFuncSetAttribute((const void*)k_mlp2final,
                         cudaFuncAttributeMaxDynamicSharedMemorySize, SM_MLP2);

    const int TB = 256;
    int gN    = (N + TB - 1) / TB;
    int gEdge = (E + TB - 1) / TB;
    int nB    = (N + 1023) / 1024;
    int gWarp = (N * 32 + TB - 1) / TB;
    int t64   = (N + 63) / 64;

    // PDL launch config (stream 0)
    cudaLaunchAttribute pdlAttr;
    pdlAttr.id = cudaLaunchAttributeProgrammaticStreamSerialization;
    pdlAttr.val.programmaticStreamSerializationAllowed = 1;
    cudaLaunchConfig_t cfg{};
    cfg.blockDim = dim3(TB, 1, 1);
    cfg.stream = 0;
    cfg.attrs = &pdlAttr;
    cfg.numAttrs = 1;

    cudaEventRecord(evStart, 0);

    // ---- CSR build on main ----
    cudaMemsetAsync(cnt, 0, (size_t)N * sizeof(int), 0);
    k_hist  <<<gEdge, TB>>>(dst, cnt, E);
    k_scan1 <<<nB,    256>>>(cnt, rp, bsum, N);
    k_scan23<<<gN,    TB>>>(cnt, rp, wp, dinv, bsum, nB, N, E);
    cudaEventRecord(evDinv, 0);

    // ---- gemm1 (needs only dinv) on main; runs alongside fill ----
    k_gemm<64,64,true,false,false,false><<<t64, TB, SM_G64>>>(
        rep, W1, nullptr, dinv, nullptr, y, N);

    // ---- fill on side stream s1 (needs wp from scan23) ----
    cudaStreamWaitEvent(s1, evDinv, 0);
    k_fill<<<gEdge, TB, 0, s1>>>(src, dst, wp, eidx, E);
    cudaEventRecord(evFill, s1);

    // ---- pre-MLP (rep @ Wa_top) on side stream s2: no dependencies ----
    cudaStreamWaitEvent(s2, evStart, 0);
    k_gemm<64,128,false,false,false,false><<<t64, TB, SM_K64M128, s2>>>(
        rep, Wa, nullptr, nullptr, nullptr, t1, N);
    cudaEventRecord(evPre, s2);

    // ---- GCN layer 1: gather needs gemm1 (in-stream) + fill ----
    cudaStreamWaitEvent(0, evFill, 0);
    k_gather<<<gWarp, TB>>>(y, rp, eidx, dinv, b1, h, N);

    // satisfy evPre early so no event wait sits inside PDL boundaries below
    cudaStreamWaitEvent(0, evPre, 0);

    // ---- GCN layer 2 (PDL: stage W2 under gather1 drain) ----
    cfg.gridDim = dim3(t64, 1, 1);
    cfg.dynamicSmemBytes = SM_G64;
    cudaLaunchKernelEx(&cfg, k_gemm<64,64,true,false,false,false>,
                       (const float*)h, W2, (const float*)nullptr,
                       (const float*)dinv, (const float*)nullptr, y2, N);

    // gather2 (PDL: launch during gemm2 drain)
    cfg.gridDim = dim3(gWarp, 1, 1);
    cfg.dynamicSmemBytes = 0;
    cudaLaunchKernelEx(&cfg, k_gather,
                       (const float*)y2, (const int*)rp, (const int*)eidx,
                       (const float*)dinv, b2, h, N);

    // ---- MLP1 second half (PDL: stage Wa_bot under gather2 drain) ----
    cfg.gridDim = dim3(t64, 1, 1);
    cfg.dynamicSmemBytes = SM_K64M128;
    cudaLaunchKernelEx(&cfg, k_gemm<64,128,false,true,true,true>,
                       (const float*)h, Wa + 64 * 128, ba,
                       (const float*)nullptr, (const float*)t1, t1, N);

    // ---- fused MLP2 + final (PDL: stage Wb under mlp1b drain) ----
    cfg.gridDim = dim3(t64, 1, 1);
    cfg.dynamicSmemBytes = SM_MLP2;
    cudaLaunchKernelEx(&cfg, k_mlp2final,
                       (const float*)t1, Wb, bb, Wo, bo, out, N);
}

// round 16
// speedup vs baseline: 1.5438x; 1.5438x over previous
#include <cuda_runtime.h>

// ---------------- problem-size constants (max) ----------------
#define N_MAX 100000
#define E_MAX 1600000

// ---------------- scratch (device globals; no allocation allowed) ----------
__device__ float g_deg [N_MAX];            // dinv
__device__ float g_y   [N_MAX * 64];       // dinv * (rep @ W1)
__device__ float g_y2  [N_MAX * 64];       // dinv * (h1 @ W2)
__device__ float g_h   [N_MAX * 64];       // h1 then h2
__device__ float g_t1  [N_MAX * 128];      // MLP hidden 1 (pre, then final)
__device__ int   g_cnt [N_MAX];            // dst histogram
__device__ int   g_rp  [N_MAX + 1];        // CSR row pointers (by dst)
__device__ int   g_wp  [N_MAX];            // fill write pointers
__device__ int   g_eidx[E_MAX];            // src ids grouped by dst
__device__ int   g_bsum[256];              // scan block partials

// ---------------- CSR build ----------------
__global__ void k_hist(const int* __restrict__ dst, int* __restrict__ cnt, int E) {
    int i = blockIdx.x * blockDim.x + threadIdx.x;
    if (i < E) atomicAdd(&cnt[dst[i]], 1);
}

__global__ void k_scan1(const int* __restrict__ cnt, int* __restrict__ rp,
                        int* __restrict__ bsum, int N) {
    __shared__ int wsum[8];
    __shared__ int btot;
    int t = threadIdx.x, lane = t & 31, w = t >> 5;
    int base = blockIdx.x * 1024 + t * 4;
    int v0 = (base + 0 < N) ? cnt[base + 0] : 0;
    int v1 = (base + 1 < N) ? cnt[base + 1] : 0;
    int v2 = (base + 2 < N) ? cnt[base + 2] : 0;
    int v3 = (base + 3 < N) ? cnt[base + 3] : 0;
    int s = v0 + v1 + v2 + v3;
    int x = s;
    #pragma unroll
    for (int o = 1; o < 32; o <<= 1) {
        int y = __shfl_up_sync(0xffffffffu, x, o);
        if (lane >= o) x += y;
    }
    if (lane == 31) wsum[w] = x;
    __syncthreads();
    if (t == 0) {
        int a = 0;
        #pragma unroll
        for (int i = 0; i < 8; ++i) { int tmp = wsum[i]; wsum[i] = a; a += tmp; }
        btot = a;
    }
    __syncthreads();
    int off = (x - s) + wsum[w];
    if (base + 0 < N) rp[base + 0] = off;
    if (base + 1 < N) rp[base + 1] = off + v0;
    if (base + 2 < N) rp[base + 2] = off + v0 + v1;
    if (base + 3 < N) rp[base + 3] = off + v0 + v1 + v2;
    if (t == 0) bsum[blockIdx.x] = btot;
}

// fused scan2+scan3
__global__ void k_scan23(const int* __restrict__ cnt, int* __restrict__ rp,
                         int* __restrict__ wp, float* __restrict__ dinv,
                         const int* __restrict__ bsum, int nB, int N, int E) {
    __shared__ int sb[128];
    __shared__ int ws[4];
    int t = threadIdx.x, lane = t & 31, w = t >> 5;
    int v = (t < nB) ? bsum[t] : 0;
    int x = v;
    #pragma unroll
    for (int o = 1; o < 32; o <<= 1) {
        int y = __shfl_up_sync(0xffffffffu, x, o);
        if (lane >= o) x += y;
    }
    if (lane == 31 && w < 4) ws[w] = x;
    __syncthreads();
    if (t == 0) {
        int a = 0;
        #pragma unroll
        for (int i = 0; i < 4; ++i) { int tmp = ws[i]; ws[i] = a; a += tmp; }
    }
    __syncthreads();
    if (t < 128) sb[t] = (x - v) + ws[w];
    __syncthreads();

    int i = blockIdx.x * blockDim.x + t;
    if (i < N) {
        int r = rp[i] + sb[i >> 10];
        rp[i] = r;
        wp[i] = r;
        dinv[i] = rsqrtf((float)cnt[i] + 2.0f);
    }
    if (i == 0) rp[N] = E;
}

__global__ void k_fill(const int* __restrict__ src, const int* __restrict__ dst,
                       int* __restrict__ wp, int* __restrict__ eidx, int E) {
    int i = blockIdx.x * blockDim.x + threadIdx.x;
    if (i < E) {
        int pos = atomicAdd(&wp[dst[i]], 1);
        eidx[pos] = src[i];
    }
}

// ---------------- fused gather + epilogue ----------------
__global__ void k_gather(const float* __restrict__ y, const int* __restrict__ rp,
                         const int* __restrict__ eidx, const float* __restrict__ dinv,
                         const float* __restrict__ b, float* __restrict__ h, int N) {
    int warp = (blockIdx.x * blockDim.x + threadIdx.x) >> 5;
    int lane = threadIdx.x & 31;
    if (warp >= N) return;
    const int c = lane * 2;
    int beg = rp[warp], end = rp[warp + 1];

    float2 a0 = *(const float2*)(y + (size_t)warp * 64 + c);
    a0.x *= 2.0f; a0.y *= 2.0f;
    float2 a1 = make_float2(0.f, 0.f);
    float2 a2 = make_float2(0.f, 0.f);
    float2 a3 = make_float2(0.f, 0.f);

    for (int j0 = beg; j0 < end; j0 += 32) {
        int myj = j0 + lane;
        int sreg = (myj < end) ? eidx[myj] : 0;
        int n = min(32, end - j0);
        int t = 0;
        for (; t + 3 < n; t += 4) {
            int s0 = __shfl_sync(0xffffffffu, sreg, t);
            int s1 = __shfl_sync(0xffffffffu, sreg, t + 1);
            int s2 = __shfl_sync(0xffffffffu, sreg, t + 2);
            int s3 = __shfl_sync(0xffffffffu, sreg, t + 3);
            float2 v0 = *(const float2*)(y + (size_t)s0 * 64 + c);
            float2 v1 = *(const float2*)(y + (size_t)s1 * 64 + c);
            float2 v2 = *(const float2*)(y + (size_t)s2 * 64 + c);
            float2 v3 = *(const float2*)(y + (size_t)s3 * 64 + c);
            a0.x += v0.x; a0.y += v0.y;
            a1.x += v1.x; a1.y += v1.y;
            a2.x += v2.x; a2.y += v2.y;
            a3.x += v3.x; a3.y += v3.y;
        }
        for (; t < n; ++t) {
            int s0 = __shfl_sync(0xffffffffu, sreg, t);
            float2 v0 = *(const float2*)(y + (size_t)s0 * 64 + c);
            a0.x += v0.x; a0.y += v0.y;
        }
    }
    float d = dinv[warp];
    float sx = (a0.x + a1.x) + (a2.x + a3.x);
    float sy = (a0.y + a1.y) + (a2.y + a3.y);
    float2 o;
    o.x = fmaxf(d * sx + b[c],     0.0f);
    o.y = fmaxf(d * sy + b[c + 1], 0.0f);
    *(float2*)(h + (size_t)warp * 64 + c) = o;
}

// ---------------- 3xTF32 helpers ----------------
__device__ __forceinline__ unsigned f2tf(float a) {
    unsigned r;
    asm("cvt.rna.tf32.f32 %0, %1;" : "=r"(r) : "f"(a));
    return r;
}

__device__ __forceinline__ void mma8(float* c, unsigned a0, unsigned a1,
                                     unsigned a2, unsigned a3,
                                     unsigned b0, unsigned b1) {
    asm("mma.sync.aligned.m16n8k8.row.col.f32.tf32.tf32.f32 "
        "{%0,%1,%2,%3},{%4,%5,%6,%7},{%8,%9},{%0,%1,%2,%3};"
        : "+f"(c[0]), "+f"(c[1]), "+f"(c[2]), "+f"(c[3])
        : "r"(a0), "r"(a1), "r"(a2), "r"(a3), "r"(b0), "r"(b1));
}

// ---------------- 3xTF32 tensor-core GEMM, 2 row-tiles per block ----------
// W staged once per block; X buffer reused across the two 64-row tiles.
template<int K, int M, bool PRESCALE, bool BIAS, bool RELU, bool ADDIN>
__global__ void __launch_bounds__(256)
k_gemm(const float* __restrict__ X0, const float* __restrict__ W,
       const float* __restrict__ bias, const float* __restrict__ dinv,
       const float* __restrict__ ADD, float* __restrict__ OUT, int N) {
    constexpr int ROWS = 64;
    constexpr int WSTR = M + 8;
    constexpr int XSTR = K + 4;
    constexpr int CPW  = M / 2;
    constexpr int NT   = CPW / 8;
    constexpr int KC   = K / 8;

    extern __shared__ float sm[];
    float* Wsm = sm;                     // K * WSTR
    float* Xs  = sm + K * WSTR;          // ROWS * XSTR

    for (int i = threadIdx.x; i < K * M; i += 256)
        Wsm[(i / M) * WSTR + (i % M)] = W[i];

    const int lane = threadIdx.x & 31;
    const int warp = threadIdx.x >> 5;
    const int q = lane & 3;
    const int g = lane >> 2;
    const int wr = warp & 3;
    const int wc = warp >> 2;
    const int cb = wc * CPW;
    const int ar0 = wr * 16 + g;

    #pragma unroll
    for (int tt = 0; tt < 2; ++tt) {
        const int row0 = (blockIdx.x * 2 + tt) * ROWS;
        if (row0 >= N) break;            // block-uniform: safe with syncs

        __syncthreads();                 // W visible (tt=0) / Xs reads done (tt=1)
        for (int i = threadIdx.x; i < ROWS * K; i += 256) {
            int r = i / K, c = i % K;
            int gr = row0 + r;
            Xs[r * XSTR + c] = (gr < N) ? X0[(size_t)gr * K + c] : 0.f;
        }
        __syncthreads();

        float acc[NT][4];
        #pragma unroll
        for (int nt = 0; nt < NT; ++nt)
            #pragma unroll
            for (int j = 0; j < 4; ++j) acc[nt][j] = 0.f;

        #pragma unroll
        for (int kc = 0; kc < KC; ++kc) {
            const int k0 = kc * 8 + q;
            float a0f = Xs[ar0 * XSTR + k0];
            float a1f = Xs[(ar0 + 8) * XSTR + k0];
            float a2f = Xs[ar0 * XSTR + k0 + 4];
            float a3f = Xs[(ar0 + 8) * XSTR + k0 + 4];
            unsigned ah0 = f2tf(a0f), ah1 = f2tf(a1f), ah2 = f2tf(a2f), ah3 = f2tf(a3f);
            unsigned al0 = f2tf(a0f - __uint_as_float(ah0));
            unsigned al1 = f2tf(a1f - __uint_as_float(ah1));
            unsigned al2 = f2tf(a2f - __uint_as_float(ah2));
            unsigned al3 = f2tf(a3f - __uint_as_float(ah3));

            #pragma unroll
            for (int nt = 0; nt < NT; ++nt) {
                int n = cb + nt * 8 + g;
                float b0f = Wsm[k0 * WSTR + n];
                float b1f = Wsm[(k0 + 4) * WSTR + n];
                unsigned bh0 = f2tf(b0f), bh1 = f2tf(b1f);
                unsigned bl0 = f2tf(b0f - __uint_as_float(bh0));
                unsigned bl1 = f2tf(b1f - __uint_as_float(bh1));
                mma8(acc[nt], al0, al1, al2, al3, bh0, bh1);  // Al*Bh
                mma8(acc[nt], ah0, ah1, ah2, ah3, bl0, bl1);  // Ah*Bl
                mma8(acc[nt], ah0, ah1, ah2, ah3, bh0, bh1);  // Ah*Bh
            }
        }

        int r0 = row0 + ar0;
        int r1 = r0 + 8;
        float s0 = 1.f, s1 = 1.f;
        if (PRESCALE) {
            if (r0 < N) s0 = dinv[r0];
            if (r1 < N) s1 = dinv[r1];
        }
        #pragma unroll
        for (int nt = 0; nt < NT; ++nt) {
            int col = cb + nt * 8 + 2 * q;
            float2 o0 = make_float2(acc[nt][0], acc[nt][1]);
            float2 o1 = make_float2(acc[nt][2], acc[nt][3]);
            if (PRESCALE) { o0.x *= s0; o0.y *= s0; o1.x *= s1; o1.y *= s1; }
            if (ADDIN) {
                if (r0 < N) {
                    float2 p = *(const float2*)(ADD + (size_t)r0 * M + col);
                    o0.x += p.x; o0.y += p.y;
                }
                if (r1 < N) {
                    float2 p = *(const float2*)(ADD + (size_t)r1 * M + col);
                    o1.x += p.x; o1.y += p.y;
                }
            }
            if (BIAS) {
                float2 b2 = *(const float2*)(bias + col);
                o0.x += b2.x; o0.y += b2.y;
                o1.x += b2.x; o1.y += b2.y;
            }
            if (RELU) {
                o0.x = fmaxf(o0.x, 0.f); o0.y = fmaxf(o0.y, 0.f);
                o1.x = fmaxf(o1.x, 0.f); o1.y = fmaxf(o1.y, 0.f);
            }
            if (r0 < N) *(float2*)(OUT + (size_t)r0 * M + col) = o0;
            if (r1 < N) *(float2*)(OUT + (size_t)r1 * M + col) = o1;
        }
    }
}

// ---------------- JAX partitionable threefry2x32 (key = [0, 42]) ----------
__device__ __forceinline__ unsigned rotl32(unsigned v, int r) {
    return (v << r) | (v >> (32 - r));
}

__device__ __forceinline__ uint2 threefry(unsigned c0, unsigned c1) {
    const unsigned k0 = 0u, k1 = 42u;
    const unsigned k2 = k0 ^ k1 ^ 0x1BD11BDAu;
    unsigned x0 = c0 + k0, x1 = c1 + k1;
#define TF_RND(r) { x0 += x1; x1 = rotl32(x1, r); x1 ^= x0; }
    TF_RND(13) TF_RND(15) TF_RND(26) TF_RND(6)
    x0 += k1; x1 += k2 + 1u;
    TF_RND(17) TF_RND(29) TF_RND(16) TF_RND(24)
    x0 += k2; x1 += k0 + 2u;
    TF_RND(13) TF_RND(15) TF_RND(26) TF_RND(6)
    x0 += k0; x1 += k1 + 3u;
    TF_RND(17) TF_RND(29) TF_RND(16) TF_RND(24)
    x0 += k1; x1 += k2 + 4u;
    TF_RND(13) TF_RND(15) TF_RND(26) TF_RND(6)
    x0 += k2; x1 += k0 + 5u;
#undef TF_RND
    return make_uint2(x0, x1);
}

__device__ __forceinline__ unsigned tf_bits_part(unsigned i) {
    uint2 o = threefry(0u, i);
    return o.x ^ o.y;
}

__device__ __forceinline__ float bits_to_uniform(unsigned b) {
    float f = __uint_as_float((b >> 9) | 0x3f800000u) - 1.0f;
    f = f + 1e-20f;
    return fmaxf(f, 1e-20f);
}

// ---------------- fused MLP2 + final (gemm K=128,M=64 + sigmoid/gumbel) ----
__global__ void __launch_bounds__(256)
k_mlp2final(const float* __restrict__ X0, const float* __restrict__ W,
            const float* __restrict__ bias, const float* __restrict__ Wo,
            const float* __restrict__ bo, float* __restrict__ out, int N) {
    constexpr int K = 128, M = 64, ROWS = 64;
    constexpr int WSTR = M + 8;
    constexpr int XSTR = K + 4;
    constexpr int CPW  = M / 2;
    constexpr int NT   = CPW / 8;
    constexpr int KC   = K / 8;
    constexpr int TSTR = 66;

    extern __shared__ float sm[];
    float* Wsm = sm;
    float* Xs  = sm + K * WSTR;
    float* t2s = Xs;

    __shared__ float ws[64];
    __shared__ float bos;

    for (int i = threadIdx.x; i < K * M; i += 256)
        Wsm[(i / M) * WSTR + (i % M)] = W[i];
    if (threadIdx.x < 64) ws[threadIdx.x] = Wo[threadIdx.x];
    if (threadIdx.x == 0) bos = bo[0];

    const int lane = threadIdx.x & 31;
    const int warp = threadIdx.x >> 5;
    const int q = lane & 3;
    const int g = lane >> 2;
    const int wr = warp & 3;
    const int wc = warp >> 2;
    const int cb = wc * CPW;
    const int row0 = blockIdx.x * ROWS;

    __syncthreads();
    for (int i = threadIdx.x; i < ROWS * K; i += 256) {
        int r = i / K, c = i % K;
        int gr = row0 + r;
        Xs[r * XSTR + c] = (gr < N) ? X0[(size_t)gr * K + c] : 0.f;
    }
    __syncthreads();

    float acc[NT][4];
    #pragma unroll
    for (int nt = 0; nt < NT; ++nt)
        #pragma unroll
        for (int j = 0; j < 4; ++j) acc[nt][j] = 0.f;

    const int ar0 = wr * 16 + g;
    #pragma unroll
    for (int kc = 0; kc < KC; ++kc) {
        const int k0 = kc * 8 + q;
        float a0f = Xs[ar0 * XSTR + k0];
        float a1f = Xs[(ar0 + 8) * XSTR + k0];
        float a2f = Xs[ar0 * XSTR + k0 + 4];
        float a3f = Xs[(ar0 + 8) * XSTR + k0 + 4];
        unsigned ah0 = f2tf(a0f), ah1 = f2tf(a1f), ah2 = f2tf(a2f), ah3 = f2tf(a3f);
        unsigned al0 = f2tf(a0f - __uint_as_float(ah0));
        unsigned al1 = f2tf(a1f - __uint_as_float(ah1));
        unsigned al2 = f2tf(a2f - __uint_as_float(ah2));
        unsigned al3 = f2tf(a3f - __uint_as_float(ah3));

        #pragma unroll
        for (int nt = 0; nt < NT; ++nt) {
            int n = cb + nt * 8 + g;
            float b0f = Wsm[k0 * WSTR + n];
            float b1f = Wsm[(k0 + 4) * WSTR + n];
            unsigned bh0 = f2tf(b0f), bh1 = f2tf(b1f);
            unsigned bl0 = f2tf(b0f - __uint_as_float(bh0));
            unsigned bl1 = f2tf(b1f - __uint_as_float(bh1));
            mma8(acc[nt], al0, al1, al2, al3, bh0, bh1);
            mma8(acc[nt], ah0, ah1, ah2, ah3, bl0, bl1);
            mma8(acc[nt], ah0, ah1, ah2, ah3, bh0, bh1);
        }
    }

    __syncthreads();

    #pragma unroll
    for (int nt = 0; nt < NT; ++nt) {
        int col = cb + nt * 8 + 2 * q;
        float2 b2 = *(const float2*)(bias + col);
        float2 o0 = make_float2(fmaxf(acc[nt][0] + b2.x, 0.f),
                                fmaxf(acc[nt][1] + b2.y, 0.f));
        float2 o1 = make_float2(fmaxf(acc[nt][2] + b2.x, 0.f),
                                fmaxf(acc[nt][3] + b2.y, 0.f));
        *(float2*)(t2s + ar0 * TSTR + col)       = o0;
        *(float2*)(t2s + (ar0 + 8) * TSTR + col) = o1;
    }
    __syncthreads();

    for (int rloc = warp; rloc < ROWS; rloc += 8) {
        int gr = row0 + rloc;
        if (gr >= N) continue;
        const float* row = t2s + rloc * TSTR;
        float s = row[lane] * ws[lane] + row[lane + 32] * ws[lane + 32];
        #pragma unroll
        for (int o = 16; o; o >>= 1) s += __shfl_xor_sync(0xffffffffu, s, o);

        float p = 1.0f / (1.0f + expf(-(s + bos)));

        float gn = 0.0f;
        if (lane < 2) {
            unsigned f = 2u * (unsigned)gr + (unsigned)lane;
            float u = bits_to_uniform(tf_bits_part(f));
            gn = -logf(-logf(u));
        }
        float g0 = __shfl_sync(0xffffffffu, gn, 0);
        float g1 = __shfl_sync(0xffffffffu, gn, 1);

        if (lane == 0) {
            out[gr]     = p;
            out[N + gr] = ((p + g1) > ((1.0f - p) + g0)) ? 1.0f : 0.0f;
        }
    }
}

// ---------------- launch ----------------
extern "C" void kernel_launch(void* const* d_in, const int* in_sizes, int n_in,
                              void* d_out, int out_size) {
    const float* rep = (const float*)d_in[0];
    const int*   ei  = (const int*)  d_in[1];
    const float* W1  = (const float*)d_in[2];
    const float* b1  = (const float*)d_in[3];
    const float* W2  = (const float*)d_in[4];
    const float* b2  = (const float*)d_in[5];
    const float* Wa  = (const float*)d_in[6];
    const float* ba  = (const float*)d_in[7];
    const float* Wb  = (const float*)d_in[8];
    const float* bb  = (const float*)d_in[9];
    const float* Wo  = (const float*)d_in[10];
    const float* bo  = (const float*)d_in[11];
    float* out = (float*)d_out;

    int N = in_sizes[0] / 64;
    int E = in_sizes[1] / 2;
    if (N > N_MAX || E > E_MAX) return;
    const int* src = ei;
    const int* dst = ei + E;

    float *dinv, *y, *y2, *h, *t1;
    int *cnt, *rp, *wp, *eidx, *bsum;
    cudaGetSymbolAddress((void**)&dinv, g_deg);
    cudaGetSymbolAddress((void**)&y,    g_y);
    cudaGetSymbolAddress((void**)&y2,   g_y2);
    cudaGetSymbolAddress((void**)&h,    g_h);
    cudaGetSymbolAddress((void**)&t1,   g_t1);
    cudaGetSymbolAddress((void**)&cnt,  g_cnt);
    cudaGetSymbolAddress((void**)&rp,   g_rp);
    cudaGetSymbolAddress((void**)&wp,   g_wp);
    cudaGetSymbolAddress((void**)&eidx, g_eidx);
    cudaGetSymbolAddress((void**)&bsum, g_bsum);

    // streams + events: created once, on the (uncaptured) correctness call
    static cudaStream_t s1 = nullptr, s2 = nullptr;
    static cudaEvent_t evStart = nullptr, evDinv = nullptr, evFill = nullptr, evPre = nullptr;
    if (!s1) {
        cudaStreamCreateWithFlags(&s1, cudaStreamNonBlocking);
        cudaStreamCreateWithFlags(&s2, cudaStreamNonBlocking);
        cudaEventCreateWithFlags(&evStart, cudaEventDisableTiming);
        cudaEventCreateWithFlags(&evDinv,  cudaEventDisableTiming);
        cudaEventCreateWithFlags(&evFill,  cudaEventDisableTiming);
        cudaEventCreateWithFlags(&evPre,   cudaEventDisableTiming);
    }

    // dynamic smem: W K*(M+8) + X 64*(K+4)
    const int SM_G64     = (64 * 72  + 64 * 68)  * 4;   // 35.8 KB
    const int SM_K64M128 = (64 * 136 + 64 * 68)  * 4;   // 52.2 KB
    const int SM_MLP2    = (128 * 72 + 64 * 132) * 4;   // 70.7 KB
    cudaFuncSetAttribute((const void*)k_gemm<64,64,true,false,false,false>,
                         cudaFuncAttributeMaxDynamicSharedMemorySize, SM_G64);
    cudaFuncSetAttribute((const void*)k_gemm<64,128,false,false,false,false>,
                         cudaFuncAttributeMaxDynamicSharedMemorySize, SM_K64M128);
    cudaFuncSetAttribute((const void*)k_gemm<64,128,false,true,true,true>,
                         cudaFuncAttributeMaxDynamicSharedMemorySize, SM_K64M128);
    cudaFuncSetAttribute((const void*)k_mlp2final,
                         cudaFuncAttributeMaxDynamicSharedMemorySize, SM_MLP2);

    const int TB = 256;
    int gN    = (N + TB - 1) / TB;
    int gEdge = (E + TB - 1) / TB;
    int nB    = (N + 1023) / 1024;
    int gWarp = (N * 32 + TB - 1) / TB;
    int t64   = (N + 63) / 64;      // mlp2final tiles (single-tile blocks)
    int t128  = (N + 127) / 128;    // k_gemm blocks (2 tiles each)

    cudaEventRecord(evStart, 0);

    // ---- CSR build on main ----
    cudaMemsetAsync(cnt, 0, (size_t)N * sizeof(int), 0);
    k_hist  <<<gEdge, TB>>>(dst, cnt, E);
    k_scan1 <<<nB,    256>>>(cnt, rp, bsum, N);
    k_scan23<<<gN,    TB>>>(cnt, rp, wp, dinv, bsum, nB, N, E);
    cudaEventRecord(evDinv, 0);

    // ---- gemm1 (needs only dinv) on main; runs alongside fill ----
    k_gemm<64,64,true,false,false,false><<<t128, TB, SM_G64>>>(
        rep, W1, nullptr, dinv, nullptr, y, N);

    // ---- fill on side stream s1 (needs wp from scan23) ----
    cudaStreamWaitEvent(s1, evDinv, 0);
    k_fill<<<gEdge, TB, 0, s1>>>(src, dst, wp, eidx, E);
    cudaEventRecord(evFill, s1);

    // ---- pre-MLP (rep @ Wa_top) on side stream s2: no dependencies ----
    cudaStreamWaitEvent(s2, evStart, 0);
    k_gemm<64,128,false,false,false,false><<<t128, TB, SM_K64M128, s2>>>(
        rep, Wa, nullptr, nullptr, nullptr, t1, N);
    cudaEventRecord(evPre, s2);

    // ---- GCN layer 1: gather needs gemm1 (in-stream) + fill ----
    cudaStreamWaitEvent(0, evFill, 0);
    k_gather<<<gWarp, TB>>>(y, rp, eidx, dinv, b1, h, N);

    // ---- GCN layer 2 ----
    k_gemm<64,64,true,false,false,false><<<t128, TB, SM_G64>>>(
        h, W2, nullptr, dinv, nullptr, y2, N);
    k_gather<<<gWarp, TB>>>(y2, rp, eidx, dinv, b2, h, N);

    // ---- MLP1 second half: t1 = relu(t1pre + h @ Wa_bot + ba), in place ----
    cudaStreamWaitEvent(0, evPre, 0);
    k_gemm<64,128,false,true,true,true><<<t128, TB, SM_K64M128>>>(
        h, Wa + 64 * 128, ba, nullptr, t1, t1, N);

    // ---- fused MLP2 + final ----
    k_mlp2final<<<t64, TB, SM_MLP2>>>(t1, Wb, bb, Wo, bo, out, N);
}